// round 11
// baseline (speedup 1.0000x reference)
#include <cuda_runtime.h>
#include <cuda_bf16.h>

// SGConv: out = (D^-1/2 A D^-1/2)^2 * feat @ W + b
// N=100000 nodes, 64 features, E=1000000 edges.
//
// Memory-guard constraints (R1/R3): big __device__ segments trigger a fixed
// 128MiB driver arena inside the checkpoint window; pre-main CUDA calls break
// harness handles (R2). => globals ~5.6MB; h1 lives in d_out; h2 lives in
// shared memory of the fused kernel.
//
// R11: ncu showed k_fused = 178.4us of 231.8 (occ 23.6%, issue 22.5%,
// L1 48.7%) -> occupancy/latency-bound at 1 block/SM (512thr x 128regs =
// full RF). Fix: GEMM tile 4x4 -> 2x4 (regs ~40), __launch_bounds__(512,2),
// nblocks = 2*SMs -> 32 warps/SM for the gather, 2x GEMM issue.
// Build + hop1 reverted to R9's exact proven forms (R10's persistent build
// cost ~12us). Only k_fused changes this round.

#define MAXN 100000
#define MAXE 1000000
#define F 64
#define SCAN_BLK 1024
#define H2S 68          // h2 row stride in floats (mult of 4 -> aligned float4)
#define SPIN_BOUND (160LL << 20)

__device__ int   g_deg[MAXN];
__device__ int   g_cur[MAXN];
__device__ int   g_rowptr[MAXN + 1];
__device__ int   g_chunksum[128];
__device__ int   g_chunkoff[128];
__device__ float g_norm[MAXN];
__device__ int   g_csr_src[MAXE];
__device__ int   g_bar;

// ---------------------------------------------------------------- zero
__global__ void k_zero(int N) {
    int i = blockIdx.x * blockDim.x + threadIdx.x;
    if (i < N) { g_deg[i] = 0; g_cur[i] = 0; }
    if (i == 0) g_bar = 0;
}

// ---------------------------------------------------------------- histogram
__global__ void k_hist(const int* __restrict__ dst, int E) {
    int e = blockIdx.x * blockDim.x + threadIdx.x;
    if (e < E) atomicAdd(&g_deg[dst[e]], 1);
}

// ---------------------------------------------------------------- scan (+norm fused)
__global__ void k_scan1(int N) {
    __shared__ int sh[SCAN_BLK];
    int t = threadIdx.x;
    int i = blockIdx.x * SCAN_BLK + t;
    int v = (i < N) ? g_deg[i] : 0;
    if (i < N) g_norm[i] = rsqrtf(fmaxf((float)v, 1.0f));   // fused norm
    sh[t] = v;
    __syncthreads();
    #pragma unroll
    for (int off = 1; off < SCAN_BLK; off <<= 1) {
        int x = (t >= off) ? sh[t - off] : 0;
        __syncthreads();
        sh[t] += x;
        __syncthreads();
    }
    if (i < N) g_rowptr[i] = sh[t] - v;          // exclusive (partial)
    if (t == SCAN_BLK - 1) g_chunksum[blockIdx.x] = sh[t];
}

// parallel exclusive scan of up to 128 chunk sums
__global__ void k_scan2(int nblocks) {
    __shared__ int sh[128];
    int t = threadIdx.x;
    int v = (t < nblocks) ? g_chunksum[t] : 0;
    sh[t] = v;
    __syncthreads();
    #pragma unroll
    for (int off = 1; off < 128; off <<= 1) {
        int x = (t >= off) ? sh[t - off] : 0;
        __syncthreads();
        sh[t] += x;
        __syncthreads();
    }
    if (t < nblocks) g_chunkoff[t] = sh[t] - v;   // exclusive
}

__global__ void k_scan3(int N, int E) {
    int i = blockIdx.x * blockDim.x + threadIdx.x;
    if (i < N) g_rowptr[i] += g_chunkoff[i / SCAN_BLK];
    if (i == 0) g_rowptr[N] = E;
}

// ---------------------------------------------------------------- CSR fill
__global__ void k_fill(const int* __restrict__ src, const int* __restrict__ dst, int E) {
    int e = blockIdx.x * blockDim.x + threadIdx.x;
    if (e < E) {
        int d = dst[e];
        int p = g_rowptr[d] + atomicAdd(&g_cur[d], 1);
        g_csr_src[p] = src[e];
    }
}

// ---------------------------------------------------------------- hop1 (R9 exact)
// one warp per dst node; lane owns float2.
__global__ void k_hop1s(const float* __restrict__ x, float* __restrict__ y, int N) {
    int warp = (blockIdx.x * blockDim.x + threadIdx.x) >> 5;
    int lane = threadIdx.x & 31;
    if (warp >= N) return;
    int beg = g_rowptr[warp];
    int end = g_rowptr[warp + 1];
    float nd = g_norm[warp];
    float2 acc = make_float2(0.f, 0.f);
    const float2* xr = (const float2*)x;
    for (int j = beg; j < end; j++) {
        int   s = __ldg(&g_csr_src[j]);
        float w = __ldg(&g_norm[s]);
        float2 v = xr[s * 32 + lane];
        acc.x += w * v.x;
        acc.y += w * v.y;
    }
    acc.x *= nd;
    acc.y *= nd;
    ((float2*)y)[warp * 32 + lane] = acc;
}

// ---------------------------------------------------------------- fused hop2 + GEMM
// 2 blocks/SM (512thr, <=64 regs, ~106KB smem each) -> 32 gather warps/SM.
// nblocks = 2*#SMs = one full wave -> all blocks co-resident -> grid barrier
// safe (bounded spin regardless). Phase 1: half-warp float4 gather into smem.
// Phase 2: 64-row tiles, 2x4 outputs/thread (keeps regs under the 64 cap).
// x and out ALIAS (= d_out); phases separated by the grid barrier.
__global__ void __launch_bounds__(512, 2)
k_fused(const float* x, float* out, const float* __restrict__ Wm,
        const float* __restrict__ bias, int N, int rows_pb, int nblocks) {
    extern __shared__ float sm[];
    float* h2 = sm;                        // rows_pb * H2S
    float* Ws = sm + rows_pb * H2S;        // 64*64

    int tid  = threadIdx.x;
    int wid  = tid >> 5;
    int lane = tid & 31;
    int half = lane >> 4;
    int lh   = lane & 15;
    int row0 = blockIdx.x * rows_pb;

    for (int i = tid; i < F * F; i += blockDim.x) Ws[i] = Wm[i];

    // ---- phase 1: half-warp gathers one row; float4 per lane (256B/row)
    const float4* xf = (const float4*)x;
    for (int lr = (wid << 1) | half; lr < rows_pb; lr += 32) {
        int r = row0 + lr;
        float4 acc = make_float4(0.f, 0.f, 0.f, 0.f);
        if (r < N) {
            int beg = g_rowptr[r];
            int end = g_rowptr[r + 1];
            float nd = g_norm[r];
            for (int j = beg; j < end; j++) {
                int   s = __ldg(&g_csr_src[j]);
                float w = __ldg(&g_norm[s]);
                float4 v = xf[s * 16 + lh];
                acc.x += w * v.x; acc.y += w * v.y;
                acc.z += w * v.z; acc.w += w * v.w;
            }
            acc.x *= nd; acc.y *= nd; acc.z *= nd; acc.w *= nd;
        }
        *(float4*)&h2[lr * H2S + 4 * lh] = acc;
    }

    // ---- software grid barrier (all blocks resident; bounded spin)
    __syncthreads();
    __threadfence();
    if (tid == 0) {
        atomicAdd(&g_bar, 1);
        long long guard = 0;
        while (*(volatile int*)&g_bar < nblocks && guard < SPIN_BOUND) {
            __nanosleep(64);
            guard++;
        }
    }
    __syncthreads();
    __threadfence();

    // ---- phase 2: out rows = h2 @ W + b, 64-row tiles, 2x4 per thread
    int tx = tid & 15;          // 16 col groups * 4 cols = 64
    int ty = tid >> 4;          // 32 row groups * 2 rows = 64 rows/tile
    int c0 = tx * 4;
    float4 bv = *(const float4*)&bias[c0];

    for (int t0 = 0; t0 < rows_pb; t0 += 64) {
        float acc[2][4];
        #pragma unroll
        for (int i = 0; i < 2; i++) {
            acc[i][0] = bv.x; acc[i][1] = bv.y; acc[i][2] = bv.z; acc[i][3] = bv.w;
        }
        int rbase = t0 + ty * 2;
        int r0c = (rbase     < rows_pb) ? rbase     : (rows_pb - 1);
        int r1c = (rbase + 1 < rows_pb) ? rbase + 1 : (rows_pb - 1);
        #pragma unroll
        for (int k = 0; k < F; k++) {
            float4 wv = *(const float4*)&Ws[k * F + c0];
            float y0 = h2[r0c * H2S + k];
            float y1 = h2[r1c * H2S + k];
            acc[0][0] += y0 * wv.x; acc[0][1] += y0 * wv.y;
            acc[0][2] += y0 * wv.z; acc[0][3] += y0 * wv.w;
            acc[1][0] += y1 * wv.x; acc[1][1] += y1 * wv.y;
            acc[1][2] += y1 * wv.z; acc[1][3] += y1 * wv.w;
        }
        #pragma unroll
        for (int i = 0; i < 2; i++) {
            int lr = rbase + i;
            int g  = row0 + lr;
            if (lr < rows_pb && g < N) {
                float4 v = make_float4(acc[i][0], acc[i][1], acc[i][2], acc[i][3]);
                *(float4*)(out + g * F + c0) = v;
            }
        }
    }
}

// ---------------------------------------------------------------- launch
extern "C" void kernel_launch(void* const* d_in, const int* in_sizes, int n_in,
                              void* d_out, int out_size) {
    const float* feat = (const float*)d_in[0];
    const int*   src  = (const int*)d_in[1];
    const int*   dst  = (const int*)d_in[2];
    const float* Wm   = (const float*)d_in[3];
    const float* bias = (const float*)d_in[4];
    float* out = (float*)d_out;

    int N = in_sizes[0] / F;   // 100000
    int E = in_sizes[1];       // 1000000

    int dev = 0;
    cudaGetDevice(&dev);
    int smcount = 0;
    cudaDeviceGetAttribute(&smcount, cudaDevAttrMultiProcessorCount, dev);
    if (smcount <= 0) smcount = 148;

    // 2 blocks per SM; smem per block must fit 2x per SM (<=228KB total).
    int nblocks = 2 * smcount;                         // 296 on B200
    int rows_pb = (N + nblocks - 1) / nblocks;         // 338
    size_t smem = (size_t)(rows_pb * H2S + F * F) * sizeof(float);  // ~106KB
    cudaFuncSetAttribute(k_fused, cudaFuncAttributeMaxDynamicSharedMemorySize,
                         (int)smem);

    int nb_n   = (N + 255) / 256;
    int nb_e   = (E + 255) / 256;
    int nb_sc  = (N + SCAN_BLK - 1) / SCAN_BLK;
    int nb_hop = (N * 32 + 255) / 256;

    k_zero<<<nb_n, 256>>>(N);
    k_hist<<<nb_e, 256>>>(dst, E);
    k_scan1<<<nb_sc, SCAN_BLK>>>(N);
    k_scan2<<<1, 128>>>(nb_sc);
    k_scan3<<<nb_n, 256>>>(N, E);
    k_fill<<<nb_e, 256>>>(src, dst, E);
    k_hop1s<<<nb_hop, 256>>>(feat, out, N);
    k_fused<<<nblocks, 512, smem>>>(out, out, Wm, bias, N, rows_pb, nblocks);
}

// round 12
// speedup vs baseline: 1.0042x; 1.0042x over previous
#include <cuda_runtime.h>
#include <cuda_bf16.h>

// SGConv: out = (D^-1/2 A D^-1/2)^2 * feat @ W + b
// N=100000 nodes, 64 features, E=1000000 edges.
//
// Memory-guard constraints (R1/R3): big __device__ segments trigger a fixed
// 128MiB driver arena inside the checkpoint window; pre-main CUDA calls break
// harness handles (R2). => globals ~5.6MB; h1 lives in d_out; h2 lives in
// shared memory of the fused kernel.
//
// R12: R11 (2 blocks/SM, 212KB smem, 64-reg cap) regressed to 440us — either
// L1D starved (16KB left) or 64-reg spills (R7/R8 signature). This round:
// 1 block/SM (same smem/L1 split as the measured-good R10), 1024 threads,
// register-thin 1x4 GEMM tile so the 64-reg cap of launch_bounds(1024,1)
// does NOT spill. -> 32 gather warps/SM (2x R10) with R10's cache behavior.
// Build + hop1 are R9-exact (219.1us baseline parts).

#define MAXN 100000
#define MAXE 1000000
#define F 64
#define SCAN_BLK 1024
#define ROWS_PB_CAP 760
#define H2S 68          // h2 row stride in floats (mult of 4 -> aligned float4)
#define SPIN_BOUND (160LL << 20)

__device__ int   g_deg[MAXN];
__device__ int   g_cur[MAXN];
__device__ int   g_rowptr[MAXN + 1];
__device__ int   g_chunksum[128];
__device__ int   g_chunkoff[128];
__device__ float g_norm[MAXN];
__device__ int   g_csr_src[MAXE];
__device__ int   g_bar;

// ---------------------------------------------------------------- zero
__global__ void k_zero(int N) {
    int i = blockIdx.x * blockDim.x + threadIdx.x;
    if (i < N) { g_deg[i] = 0; g_cur[i] = 0; }
    if (i == 0) g_bar = 0;
}

// ---------------------------------------------------------------- histogram
__global__ void k_hist(const int* __restrict__ dst, int E) {
    int e = blockIdx.x * blockDim.x + threadIdx.x;
    if (e < E) atomicAdd(&g_deg[dst[e]], 1);
}

// ---------------------------------------------------------------- scan (+norm fused)
__global__ void k_scan1(int N) {
    __shared__ int sh[SCAN_BLK];
    int t = threadIdx.x;
    int i = blockIdx.x * SCAN_BLK + t;
    int v = (i < N) ? g_deg[i] : 0;
    if (i < N) g_norm[i] = rsqrtf(fmaxf((float)v, 1.0f));   // fused norm
    sh[t] = v;
    __syncthreads();
    #pragma unroll
    for (int off = 1; off < SCAN_BLK; off <<= 1) {
        int x = (t >= off) ? sh[t - off] : 0;
        __syncthreads();
        sh[t] += x;
        __syncthreads();
    }
    if (i < N) g_rowptr[i] = sh[t] - v;          // exclusive (partial)
    if (t == SCAN_BLK - 1) g_chunksum[blockIdx.x] = sh[t];
}

// parallel exclusive scan of up to 128 chunk sums
__global__ void k_scan2(int nblocks) {
    __shared__ int sh[128];
    int t = threadIdx.x;
    int v = (t < nblocks) ? g_chunksum[t] : 0;
    sh[t] = v;
    __syncthreads();
    #pragma unroll
    for (int off = 1; off < 128; off <<= 1) {
        int x = (t >= off) ? sh[t - off] : 0;
        __syncthreads();
        sh[t] += x;
        __syncthreads();
    }
    if (t < nblocks) g_chunkoff[t] = sh[t] - v;   // exclusive
}

__global__ void k_scan3(int N, int E) {
    int i = blockIdx.x * blockDim.x + threadIdx.x;
    if (i < N) g_rowptr[i] += g_chunkoff[i / SCAN_BLK];
    if (i == 0) g_rowptr[N] = E;
}

// ---------------------------------------------------------------- CSR fill
__global__ void k_fill(const int* __restrict__ src, const int* __restrict__ dst, int E) {
    int e = blockIdx.x * blockDim.x + threadIdx.x;
    if (e < E) {
        int d = dst[e];
        int p = g_rowptr[d] + atomicAdd(&g_cur[d], 1);
        g_csr_src[p] = src[e];
    }
}

// ---------------------------------------------------------------- hop1 (R9 exact)
// one warp per dst node; lane owns float2.
__global__ void k_hop1s(const float* __restrict__ x, float* __restrict__ y, int N) {
    int warp = (blockIdx.x * blockDim.x + threadIdx.x) >> 5;
    int lane = threadIdx.x & 31;
    if (warp >= N) return;
    int beg = g_rowptr[warp];
    int end = g_rowptr[warp + 1];
    float nd = g_norm[warp];
    float2 acc = make_float2(0.f, 0.f);
    const float2* xr = (const float2*)x;
    for (int j = beg; j < end; j++) {
        int   s = __ldg(&g_csr_src[j]);
        float w = __ldg(&g_norm[s]);
        float2 v = xr[s * 32 + lane];
        acc.x += w * v.x;
        acc.y += w * v.y;
    }
    acc.x *= nd;
    acc.y *= nd;
    ((float2*)y)[warp * 32 + lane] = acc;
}

// ---------------------------------------------------------------- fused hop2 + GEMM
// 1 block/SM (same ~196KB smem / L1 split as measured-good R10), 1024 thr ->
// 32 gather warps/SM. GEMM phase uses a register-thin 1x4 tile so the 64-reg
// cap of launch_bounds(1024,1) does not spill (R7/R8 spilled only with the
// fat 4x4 tile). nblocks <= #SMs -> all blocks resident -> barrier safe.
// x and out ALIAS (= d_out); phases separated by the grid barrier.
__global__ void __launch_bounds__(1024, 1)
k_fused(const float* x, float* out, const float* __restrict__ Wm,
        const float* __restrict__ bias, int N, int rows_pb, int nblocks) {
    extern __shared__ float sm[];
    float* h2 = sm;                        // rows_pb * H2S
    float* Ws = sm + rows_pb * H2S;        // 64*64

    int tid  = threadIdx.x;
    int wid  = tid >> 5;
    int lane = tid & 31;
    int half = lane >> 4;
    int lh   = lane & 15;
    int row0 = blockIdx.x * rows_pb;

    for (int i = tid; i < F * F; i += blockDim.x) Ws[i] = Wm[i];

    // ---- phase 1: half-warp gathers one row; float4 per lane (256B/row)
    // 32 warps -> 64 concurrent row streams per block.
    const float4* xf = (const float4*)x;
    for (int lr = (wid << 1) | half; lr < rows_pb; lr += 64) {
        int r = row0 + lr;
        float4 acc = make_float4(0.f, 0.f, 0.f, 0.f);
        if (r < N) {
            int beg = g_rowptr[r];
            int end = g_rowptr[r + 1];
            float nd = g_norm[r];
            for (int j = beg; j < end; j++) {
                int   s = __ldg(&g_csr_src[j]);
                float w = __ldg(&g_norm[s]);
                float4 v = xf[s * 16 + lh];
                acc.x += w * v.x; acc.y += w * v.y;
                acc.z += w * v.z; acc.w += w * v.w;
            }
            acc.x *= nd; acc.y *= nd; acc.z *= nd; acc.w *= nd;
        }
        *(float4*)&h2[lr * H2S + 4 * lh] = acc;
    }

    // ---- software grid barrier (all blocks resident; bounded spin)
    __syncthreads();
    __threadfence();
    if (tid == 0) {
        atomicAdd(&g_bar, 1);
        long long guard = 0;
        while (*(volatile int*)&g_bar < nblocks && guard < SPIN_BOUND) {
            __nanosleep(64);
            guard++;
        }
    }
    __syncthreads();
    __threadfence();

    // ---- phase 2: out rows = h2 @ W + b, 64-row tiles, 1x4 per thread
    int tx = tid & 15;          // 16 col groups * 4 cols = 64
    int ty = tid >> 4;          // 64 row groups * 1 row  = 64 rows/tile
    int c0 = tx * 4;
    float4 bv = *(const float4*)&bias[c0];

    for (int t0 = 0; t0 < rows_pb; t0 += 64) {
        float a0 = bv.x, a1 = bv.y, a2 = bv.z, a3 = bv.w;
        int lr = t0 + ty;
        int rc = (lr < rows_pb) ? lr : (rows_pb - 1);   // clamp smem reads
        const float* hrow = &h2[rc * H2S];
        #pragma unroll
        for (int k = 0; k < F; k++) {
            float4 wv = *(const float4*)&Ws[k * F + c0];
            float yv = hrow[k];
            a0 += yv * wv.x;
            a1 += yv * wv.y;
            a2 += yv * wv.z;
            a3 += yv * wv.w;
        }
        int g = row0 + lr;
        if (lr < rows_pb && g < N) {
            float4 v = make_float4(a0, a1, a2, a3);
            *(float4*)(out + g * F + c0) = v;
        }
    }
}

// ---------------------------------------------------------------- launch
extern "C" void kernel_launch(void* const* d_in, const int* in_sizes, int n_in,
                              void* d_out, int out_size) {
    const float* feat = (const float*)d_in[0];
    const int*   src  = (const int*)d_in[1];
    const int*   dst  = (const int*)d_in[2];
    const float* Wm   = (const float*)d_in[3];
    const float* bias = (const float*)d_in[4];
    float* out = (float*)d_out;

    int N = in_sizes[0] / F;   // 100000
    int E = in_sizes[1];       // 1000000

    int dev = 0;
    cudaGetDevice(&dev);
    int smcount = 0;
    cudaDeviceGetAttribute(&smcount, cudaDevAttrMultiProcessorCount, dev);
    if (smcount <= 0) smcount = 148;

    int rows_pb = (N + smcount - 1) / smcount;        // 676 @148
    if (rows_pb > ROWS_PB_CAP) rows_pb = ROWS_PB_CAP;
    int nblocks = (N + rows_pb - 1) / rows_pb;        // <= smcount
    if (nblocks > smcount) nblocks = smcount;
    rows_pb = (N + nblocks - 1) / nblocks;
    size_t smem = (size_t)(rows_pb * H2S + F * F) * sizeof(float);  // ~196KB
    cudaFuncSetAttribute(k_fused, cudaFuncAttributeMaxDynamicSharedMemorySize,
                         (int)smem);

    int nb_n   = (N + 255) / 256;
    int nb_e   = (E + 255) / 256;
    int nb_sc  = (N + SCAN_BLK - 1) / SCAN_BLK;
    int nb_hop = (N * 32 + 255) / 256;

    k_zero<<<nb_n, 256>>>(N);
    k_hist<<<nb_e, 256>>>(dst, E);
    k_scan1<<<nb_sc, SCAN_BLK>>>(N);
    k_scan2<<<1, 128>>>(nb_sc);
    k_scan3<<<nb_n, 256>>>(N, E);
    k_fill<<<nb_e, 256>>>(src, dst, E);
    k_hop1s<<<nb_hop, 256>>>(feat, out, N);
    k_fused<<<nblocks, 1024, smem>>>(out, out, Wm, bias, N, rows_pb, nblocks);
}

// round 14
// speedup vs baseline: 2.6548x; 2.6438x over previous
#include <cuda_runtime.h>
#include <cuda_bf16.h>

// SGConv: out = (D^-1/2 A D^-1/2)^2 * feat @ W + b
// N=100000, F=64, E=1000000.
//
// R14 = R13 resubmit (R13 died to broker-level container failure, pattern
// matches R4/R6 which passed on resubmit). One hardening: the
// cudaGetSymbolAddress call inside kernel_launch is removed (runtime API
// during the harness's stream capture is a capture-invalidation risk on some
// drivers); k_hopq takes a to_scratch flag and addresses g_q from device
// code. kernel_launch is now launches-only.
//
// Design (R13): persistent fused hop2+GEMM abandoned — six configs proved
// its gather is crippled (16 warps/SM @128regs -> 178us; any 32-warp config
// needs a 64-reg cap -> ~440us). hop2 is column-separable -> 4 quarter
// passes with disjoint read/write column sets -> race-free, barrier-free,
// full occupancy:
//   P1: h1.q0 (d_out) -> g_q        P2: h1.q1 -> d_out.q0
//   P3: h1.q2 -> d_out.q1           P4: h1.q3 -> d_out.q2
// GEMM (row-local, in-place): h2 row = [g_q | d_out cols 0..47], x W + b.
// GEMM tail re-zeros deg/cur for the next call (globals zero-init at load).
// Globals: 12.0MB total (probes the 128MiB-arena threshold; safe 5.6MB,
// bad 35.2MB).

#define MAXN 100000
#define MAXE 1000000
#define F 64
#define SCAN_BLK 1024

__device__ int   g_deg[MAXN];        // zero at entry (load-init / gemm tail)
__device__ int   g_cur[MAXN];        // zero at entry
__device__ int   g_rowptr[MAXN + 1];
__device__ int   g_chunksum[128];
__device__ float g_norm[MAXN];
__device__ int   g_csr_src[MAXE];
__device__ float g_q[MAXN * 16];     // h2 quarter scratch, 6.4MB

// ---------------------------------------------------------------- histogram
__global__ void k_hist(const int* __restrict__ dst, int E) {
    int e = blockIdx.x * blockDim.x + threadIdx.x;
    if (e < E) atomicAdd(&g_deg[dst[e]], 1);
}

// ---------------------------------------------------------------- scan1 (+norm)
__global__ void k_scan1(int N) {
    __shared__ int sh[SCAN_BLK];
    int t = threadIdx.x;
    int i = blockIdx.x * SCAN_BLK + t;
    int v = (i < N) ? g_deg[i] : 0;
    if (i < N) g_norm[i] = rsqrtf(fmaxf((float)v, 1.0f));
    sh[t] = v;
    __syncthreads();
    #pragma unroll
    for (int off = 1; off < SCAN_BLK; off <<= 1) {
        int x = (t >= off) ? sh[t - off] : 0;
        __syncthreads();
        sh[t] += x;
        __syncthreads();
    }
    if (i < N) g_rowptr[i] = sh[t] - v;              // exclusive (partial)
    if (t == SCAN_BLK - 1) g_chunksum[blockIdx.x] = sh[t];
}

// ---------------------------------------------------------------- scan2+3 merged
// every block redundantly scans the <=128 chunk sums in smem, then applies
// the offset to its rowptr slice.
__global__ void k_scan23(int N, int E, int nchunks) {
    __shared__ int sh[128];
    int t = threadIdx.x;                      // 256 threads
    if (t < 128) sh[t] = (t < nchunks) ? g_chunksum[t] : 0;
    __syncthreads();
    #pragma unroll
    for (int off = 1; off < 128; off <<= 1) {
        int x = (t >= off && t < 128) ? sh[t - off] : 0;
        __syncthreads();
        if (t < 128) sh[t] += x;
        __syncthreads();
    }
    int i = blockIdx.x * blockDim.x + t;
    if (i < N) {
        int chunk = i / SCAN_BLK;
        int off = (chunk == 0) ? 0 : sh[chunk - 1];
        g_rowptr[i] += off;
    }
    if (i == 0) g_rowptr[N] = E;
}

// ---------------------------------------------------------------- CSR fill
__global__ void k_fill(const int* __restrict__ src, const int* __restrict__ dst, int E) {
    int e = blockIdx.x * blockDim.x + threadIdx.x;
    if (e < E) {
        int d = dst[e];
        int p = g_rowptr[d] + atomicAdd(&g_cur[d], 1);
        g_csr_src[p] = src[e];
    }
}

// ---------------------------------------------------------------- hop1 (R9 exact)
// one warp per dst node; lane owns float2 (256B/row).
__global__ void k_hop1s(const float* __restrict__ x, float* __restrict__ y, int N) {
    int warp = (blockIdx.x * blockDim.x + threadIdx.x) >> 5;
    int lane = threadIdx.x & 31;
    if (warp >= N) return;
    int beg = g_rowptr[warp];
    int end = g_rowptr[warp + 1];
    float nd = g_norm[warp];
    float2 acc = make_float2(0.f, 0.f);
    const float2* xr = (const float2*)x;
    for (int j = beg; j < end; j++) {
        int   s = __ldg(&g_csr_src[j]);
        float w = __ldg(&g_norm[s]);
        float2 v = xr[s * 32 + lane];
        acc.x += w * v.x;
        acc.y += w * v.y;
    }
    acc.x *= nd;
    acc.y *= nd;
    ((float2*)y)[warp * 32 + lane] = acc;
}

// ---------------------------------------------------------------- hop2 quarter pass
// half-warp per dst row; lane owns 1 float of a 16-col quarter (64B/row).
// read columns and write columns are disjoint -> race-free in-flight.
// to_scratch=1: write g_q[row][lh] (device symbol, no host symbol lookup);
// else write ydst[row*F + lh].
__global__ void k_hopq(const float* __restrict__ xsrc, float* ydst,
                       int to_scratch, int N) {
    int idx = blockIdx.x * blockDim.x + threadIdx.x;
    int row = idx >> 4;
    int lh  = idx & 15;
    if (row >= N) return;
    int beg = g_rowptr[row];
    int end = g_rowptr[row + 1];
    float nd = g_norm[row];
    float acc = 0.f;
    for (int j = beg; j < end; j++) {
        int   s = __ldg(&g_csr_src[j]);
        float w = __ldg(&g_norm[s]);
        acc += w * xsrc[s * F + lh];
    }
    acc *= nd;
    if (to_scratch) g_q[row * 16 + lh] = acc;
    else            ydst[row * F + lh] = acc;
}

// ---------------------------------------------------------------- GEMM (in-place, row-local)
// 64-row tile, 256 threads, 4x4 outputs/thread (R5-proven shape).
// h2 row r = [ g_q[r][0..15] | inout[r][0..47] ]  (quarters 1-3 parked there).
// Tail: re-zero deg/cur for the next kernel_launch call.
__global__ void k_gemm(float* inout, const float* __restrict__ Wm,
                       const float* __restrict__ bias, int N) {
    __shared__ float Ws[F][F];        // 16KB
    __shared__ float Ys[F][F + 1];    // padded, ~16.6KB
    int t = threadIdx.x;
    int row0 = blockIdx.x * F;
    for (int i = t; i < F * F; i += 256)
        Ws[i >> 6][i & 63] = Wm[i];
    for (int i = t; i < F * F; i += 256) {
        int r = i >> 6, c = i & 63;
        int gr = row0 + r;
        float v = 0.f;
        if (gr < N)
            v = (c < 16) ? g_q[gr * 16 + c] : inout[gr * F + (c - 16)];
        Ys[r][c] = v;
    }
    __syncthreads();
    int tx = t & 15, ty = t >> 4;
    int c0 = tx * 4, r0 = ty * 4;
    float acc[4][4];
    float4 bv = *(const float4*)&bias[c0];
    #pragma unroll
    for (int i = 0; i < 4; i++) {
        acc[i][0] = bv.x; acc[i][1] = bv.y; acc[i][2] = bv.z; acc[i][3] = bv.w;
    }
    #pragma unroll
    for (int k = 0; k < F; k++) {
        float4 wv = *(const float4*)&Ws[k][c0];
        #pragma unroll
        for (int i = 0; i < 4; i++) {
            float yv = Ys[r0 + i][k];
            acc[i][0] += yv * wv.x;
            acc[i][1] += yv * wv.y;
            acc[i][2] += yv * wv.z;
            acc[i][3] += yv * wv.w;
        }
    }
    #pragma unroll
    for (int i = 0; i < 4; i++) {
        int gr = row0 + r0 + i;
        if (gr < N) {
            float4 v = make_float4(acc[i][0], acc[i][1], acc[i][2], acc[i][3]);
            *(float4*)(inout + gr * F + c0) = v;
        }
    }
    // re-zero counters for the next call (globals are zero-init at load,
    // so call 1 is covered; this keeps every call's entry state identical).
    int gi = blockIdx.x * 256 + t;
    if (gi < N) { g_deg[gi] = 0; g_cur[gi] = 0; }
}

// ---------------------------------------------------------------- launch
// Launches ONLY — no runtime API calls (graph-capture strictness).
extern "C" void kernel_launch(void* const* d_in, const int* in_sizes, int n_in,
                              void* d_out, int out_size) {
    const float* feat = (const float*)d_in[0];
    const int*   src  = (const int*)d_in[1];
    const int*   dst  = (const int*)d_in[2];
    const float* Wm   = (const float*)d_in[3];
    const float* bias = (const float*)d_in[4];
    float* out = (float*)d_out;

    int N = in_sizes[0] / F;   // 100000
    int E = in_sizes[1];       // 1000000

    int nb_e   = (E + 255) / 256;
    int nb_sc  = (N + SCAN_BLK - 1) / SCAN_BLK;
    int nb_n   = (N + 255) / 256;
    int nb_h1  = (N * 32 + 255) / 256;
    int nb_hq  = (N * 16 + 255) / 256;
    int nb_gm  = (N + F - 1) / F;

    k_hist  <<<nb_e,  256>>>(dst, E);
    k_scan1 <<<nb_sc, SCAN_BLK>>>(N);
    k_scan23<<<nb_n,  256>>>(N, E, nb_sc);
    k_fill  <<<nb_e,  256>>>(src, dst, E);          // ncu capture idx 3
    k_hop1s <<<nb_h1, 256>>>(feat, out, N);
    // hop2 quarter passes: disjoint column read/write sets, no races
    k_hopq  <<<nb_hq, 256>>>(out + 0,  nullptr,  1, N);  // q0 -> g_q scratch
    k_hopq  <<<nb_hq, 256>>>(out + 16, out + 0,  0, N);  // q1 -> dout.q0
    k_hopq  <<<nb_hq, 256>>>(out + 32, out + 16, 0, N);  // q2 -> dout.q1
    k_hopq  <<<nb_hq, 256>>>(out + 48, out + 32, 0, N);  // q3 -> dout.q2
    k_gemm  <<<nb_gm, 256>>>(out, Wm, bias, N);
}

// round 16
// speedup vs baseline: 2.9431x; 1.1086x over previous
#include <cuda_runtime.h>
#include <cuda_bf16.h>

// SGConv: out = (D^-1/2 A D^-1/2)^2 * feat @ W + b
// N=100000, F=64, E=1000000.
//
// R16 = R15 resubmit (R15 died to broker-level container failure; 4th
// occurrence, every prior one passed on unchanged resubmit — R4->R5,
// R6->R7, R13->R14). Code is R15-equivalent.
//
// R15 deltas vs R14 (165.9us):
//  - scan23 fused into fill (k_fill2 redundantly scans 98 chunk sums in smem;
//    block 0 publishes g_choff; consumers add choff[r>>10]) -> one fewer
//    launch AND k_hop1s becomes the profiled 4th launch.
//  - hist/fill process 4 edges/thread (int4) -> MLP 4 on the atomic chains.
//  - scan1 rewritten with warp shuffles (2 syncs, was 20).
//  - g_cur eliminated: g_deg zeroed in scan1 (after read) and reused as the
//    fill cursor; GEMM tail re-zeros g_deg. Globals 11.6MB (<= proven-safe
//    12.0MB; arena threshold bracketed (12.0, 35.2]).
//  - GEMM Ys loads vectorized (float4, stride 68).

#define MAXN 100000
#define MAXE 1000000
#define F 64
#define NCHUNK 128       // >= ceil(N/1024) = 98

__device__ int   g_deg[MAXN];        // zero at entry; scan1 re-zeroes; fill uses as cursor
__device__ int   g_rowptr[MAXN + 1]; // chunk-partial exclusive scan (scan1)
__device__ int   g_chunksum[NCHUNK];
__device__ int   g_choff[NCHUNK];    // exclusive chunk offsets (published by fill2 blk0)
__device__ float g_norm[MAXN];
__device__ int   g_csr_src[MAXE];
__device__ float g_q[MAXN * 16];     // h2 quarter scratch, 6.4MB

// ---------------------------------------------------------------- histogram (4 edges/thread)
__global__ void k_hist(const int* __restrict__ dst, int E) {
    int base = (blockIdx.x * blockDim.x + threadIdx.x) * 4;
    if (base + 3 < E) {
        int4 d = *(const int4*)(dst + base);
        atomicAdd(&g_deg[d.x], 1);
        atomicAdd(&g_deg[d.y], 1);
        atomicAdd(&g_deg[d.z], 1);
        atomicAdd(&g_deg[d.w], 1);
    } else {
        for (int e = base; e < E; e++) atomicAdd(&g_deg[dst[e]], 1);
    }
}

// ---------------------------------------------------------------- scan1 (shuffle scan + norm + deg re-zero)
__global__ void k_scan1(int N) {
    __shared__ int swarp[32];
    int t = threadIdx.x;                    // 1024 threads
    int i = blockIdx.x * 1024 + t;
    int v = (i < N) ? g_deg[i] : 0;
    if (i < N) {
        g_norm[i] = rsqrtf(fmaxf((float)v, 1.0f));
        g_deg[i] = 0;                       // becomes the fill cursor
    }
    int lane = t & 31, wid = t >> 5;
    int s = v;
    #pragma unroll
    for (int o = 1; o < 32; o <<= 1) {
        int x = __shfl_up_sync(0xffffffffu, s, o);
        if (lane >= o) s += x;
    }
    if (lane == 31) swarp[wid] = s;
    __syncthreads();
    if (wid == 0) {
        int ws = swarp[lane];
        #pragma unroll
        for (int o = 1; o < 32; o <<= 1) {
            int x = __shfl_up_sync(0xffffffffu, ws, o);
            if (lane >= o) ws += x;
        }
        swarp[lane] = ws;                   // inclusive warp totals
    }
    __syncthreads();
    int incl = s + ((wid > 0) ? swarp[wid - 1] : 0);
    if (i < N) g_rowptr[i] = incl - v;      // exclusive, chunk-partial
    if (i == N - 1) g_rowptr[N] = incl;     // partial inclusive at N-1
    if (t == 1023) g_chunksum[blockIdx.x] = incl;   // chunk total
}

// ---------------------------------------------------------------- fill (+chunk-offset finalize)
// Each block redundantly scans the chunk sums in smem; block 0 publishes
// g_choff (exclusive offsets) for the downstream hop kernels.
__global__ void k_fill2(const int* __restrict__ src, const int* __restrict__ dst,
                        int E, int nchunks) {
    __shared__ int soff[NCHUNK];            // inclusive scan of chunk sums
    int t = threadIdx.x;                    // 256 threads
    if (t < NCHUNK) soff[t] = (t < nchunks) ? g_chunksum[t] : 0;
    __syncthreads();
    #pragma unroll
    for (int o = 1; o < NCHUNK; o <<= 1) {
        int x = (t >= o && t < NCHUNK) ? soff[t - o] : 0;
        __syncthreads();
        if (t < NCHUNK) soff[t] += x;
        __syncthreads();
    }
    if (blockIdx.x == 0 && t < NCHUNK)
        g_choff[t] = (t == 0) ? 0 : soff[t - 1];    // exclusive, for consumers
    __syncthreads();

    int base = (blockIdx.x * blockDim.x + t) * 4;
    if (base + 3 < E) {
        int4 d4 = *(const int4*)(dst + base);
        int4 s4 = *(const int4*)(src + base);
        {
            int d = d4.x, c = d >> 10;
            int p = g_rowptr[d] + ((c == 0) ? 0 : soff[c - 1]) + atomicAdd(&g_deg[d], 1);
            g_csr_src[p] = s4.x;
        }
        {
            int d = d4.y, c = d >> 10;
            int p = g_rowptr[d] + ((c == 0) ? 0 : soff[c - 1]) + atomicAdd(&g_deg[d], 1);
            g_csr_src[p] = s4.y;
        }
        {
            int d = d4.z, c = d >> 10;
            int p = g_rowptr[d] + ((c == 0) ? 0 : soff[c - 1]) + atomicAdd(&g_deg[d], 1);
            g_csr_src[p] = s4.z;
        }
        {
            int d = d4.w, c = d >> 10;
            int p = g_rowptr[d] + ((c == 0) ? 0 : soff[c - 1]) + atomicAdd(&g_deg[d], 1);
            g_csr_src[p] = s4.w;
        }
    } else {
        for (int e = base; e < E; e++) {
            int d = dst[e], c = d >> 10;
            int p = g_rowptr[d] + ((c == 0) ? 0 : soff[c - 1]) + atomicAdd(&g_deg[d], 1);
            g_csr_src[p] = src[e];
        }
    }
}

// ---------------------------------------------------------------- hop1 (4th launch -> profiled)
// one warp per dst node; lane owns float2 (256B/row). rowptr finalized on
// the fly via g_choff (L1-hot).
__global__ void k_hop1s(const float* __restrict__ x, float* __restrict__ y, int N) {
    int warp = (blockIdx.x * blockDim.x + threadIdx.x) >> 5;
    int lane = threadIdx.x & 31;
    if (warp >= N) return;
    int beg = g_rowptr[warp]     + g_choff[warp >> 10];
    int end = g_rowptr[warp + 1] + g_choff[(warp + 1) >> 10];
    float nd = g_norm[warp];
    float2 acc = make_float2(0.f, 0.f);
    const float2* xr = (const float2*)x;
    for (int j = beg; j < end; j++) {
        int   s = __ldg(&g_csr_src[j]);
        float w = __ldg(&g_norm[s]);
        float2 v = xr[s * 32 + lane];
        acc.x += w * v.x;
        acc.y += w * v.y;
    }
    acc.x *= nd;
    acc.y *= nd;
    ((float2*)y)[warp * 32 + lane] = acc;
}

// ---------------------------------------------------------------- hop2 quarter pass
// half-warp per dst row; lane owns 1 float of a 16-col quarter.
// read/write column sets disjoint -> race-free.
__global__ void k_hopq(const float* __restrict__ xsrc, float* ydst,
                       int to_scratch, int N) {
    int idx = blockIdx.x * blockDim.x + threadIdx.x;
    int row = idx >> 4;
    int lh  = idx & 15;
    if (row >= N) return;
    int beg = g_rowptr[row]     + g_choff[row >> 10];
    int end = g_rowptr[row + 1] + g_choff[(row + 1) >> 10];
    float nd = g_norm[row];
    float acc = 0.f;
    for (int j = beg; j < end; j++) {
        int   s = __ldg(&g_csr_src[j]);
        float w = __ldg(&g_norm[s]);
        acc += w * xsrc[s * F + lh];
    }
    acc *= nd;
    if (to_scratch) g_q[row * 16 + lh] = acc;
    else            ydst[row * F + lh] = acc;
}

// ---------------------------------------------------------------- GEMM (in-place, row-local)
// 64-row tile, 256 threads, 4x4 outputs/thread. Ys loads via float4.
// h2 row r = [ g_q[r][0..15] | inout[r][0..47] ]. Tail re-zeros g_deg.
__global__ void k_gemm(float* inout, const float* __restrict__ Wm,
                       const float* __restrict__ bias, int N) {
    __shared__ float Ws[F][F];         // 16KB
    __shared__ float Ys[F][68];        // stride 68: float4-aligned rows
    int t = threadIdx.x;
    int row0 = blockIdx.x * F;
    for (int i = t; i < F * F / 4; i += 256) {
        *(float4*)&((float*)Ws)[i * 4] = *(const float4*)&Wm[i * 4];
    }
    for (int i4 = t; i4 < F * 16; i4 += 256) {      // 16 float4 per row
        int r  = i4 >> 4;
        int c4 = (i4 & 15) * 4;
        int gr = row0 + r;
        float4 v = make_float4(0.f, 0.f, 0.f, 0.f);
        if (gr < N)
            v = (c4 < 16) ? *(const float4*)&g_q[gr * 16 + c4]
                          : *(const float4*)&inout[gr * F + (c4 - 16)];
        *(float4*)&Ys[r][c4] = v;
    }
    __syncthreads();
    int tx = t & 15, ty = t >> 4;
    int c0 = tx * 4, r0 = ty * 4;
    float acc[4][4];
    float4 bv = *(const float4*)&bias[c0];
    #pragma unroll
    for (int i = 0; i < 4; i++) {
        acc[i][0] = bv.x; acc[i][1] = bv.y; acc[i][2] = bv.z; acc[i][3] = bv.w;
    }
    #pragma unroll
    for (int k = 0; k < F; k++) {
        float4 wv = *(const float4*)&Ws[k][c0];
        #pragma unroll
        for (int i = 0; i < 4; i++) {
            float yv = Ys[r0 + i][k];
            acc[i][0] += yv * wv.x;
            acc[i][1] += yv * wv.y;
            acc[i][2] += yv * wv.z;
            acc[i][3] += yv * wv.w;
        }
    }
    #pragma unroll
    for (int i = 0; i < 4; i++) {
        int gr = row0 + r0 + i;
        if (gr < N) {
            float4 v = make_float4(acc[i][0], acc[i][1], acc[i][2], acc[i][3]);
            *(float4*)(inout + gr * F + c0) = v;
        }
    }
    // re-zero the deg/cursor array for the next call (zero-init covers call 1)
    int gi = blockIdx.x * 256 + t;
    if (gi < N) g_deg[gi] = 0;
}

// ---------------------------------------------------------------- launch
// Launches ONLY — no runtime API calls (graph-capture strictness).
extern "C" void kernel_launch(void* const* d_in, const int* in_sizes, int n_in,
                              void* d_out, int out_size) {
    const float* feat = (const float*)d_in[0];
    const int*   src  = (const int*)d_in[1];
    const int*   dst  = (const int*)d_in[2];
    const float* Wm   = (const float*)d_in[3];
    const float* bias = (const float*)d_in[4];
    float* out = (float*)d_out;

    int N = in_sizes[0] / F;   // 100000
    int E = in_sizes[1];       // 1000000

    int nb_e4  = (E / 4 + 255) / 256;
    int nb_sc  = (N + 1023) / 1024;        // 98 chunks
    int nb_h1  = (N * 32 + 255) / 256;
    int nb_hq  = (N * 16 + 255) / 256;
    int nb_gm  = (N + F - 1) / F;

    k_hist  <<<nb_e4, 256>>>(dst, E);
    k_scan1 <<<nb_sc, 1024>>>(N);
    k_fill2 <<<nb_e4, 256>>>(src, dst, E, nb_sc);
    k_hop1s <<<nb_h1, 256>>>(feat, out, N);         // 4th launch: profiled
    // hop2 quarter passes: disjoint column read/write sets, no races
    k_hopq  <<<nb_hq, 256>>>(out + 0,  nullptr,  1, N);  // q0 -> g_q scratch
    k_hopq  <<<nb_hq, 256>>>(out + 16, out + 0,  0, N);  // q1 -> dout.q0
    k_hopq  <<<nb_hq, 256>>>(out + 32, out + 16, 0, N);  // q2 -> dout.q1
    k_hopq  <<<nb_hq, 256>>>(out + 48, out + 32, 0, N);  // q3 -> dout.q2
    k_gemm  <<<nb_gm, 256>>>(out, Wm, bias, N);
}

// round 17
// speedup vs baseline: 3.2101x; 1.0907x over previous
#include <cuda_runtime.h>
#include <cuda_bf16.h>

// SGConv: out = (D^-1/2 A D^-1/2)^2 * feat @ W + b
// N=100000, F=64, E=1000000.
//
// R17 vs R16 (149.7us): hop kernels are ISSUE-bound (hop1s: 35.8us,
// issue 46.6%, L2 35%, DRAM 11% -> not BW). Fix = multi-row warps so one
// issued instruction serves several rows:
//  - k_hop1s: half-warp x float4 (2 rows/warp, R9-proven form).
//  - k_hopq:  8-lane groups x float2 (4 rows/warp).
// Everything else identical to R16. Globals 11.6MB (proven safe).

#define MAXN 100000
#define MAXE 1000000
#define F 64
#define NCHUNK 128       // >= ceil(N/1024) = 98

__device__ int   g_deg[MAXN];        // zero at entry; scan1 re-zeroes; fill uses as cursor
__device__ int   g_rowptr[MAXN + 1]; // chunk-partial exclusive scan (scan1)
__device__ int   g_chunksum[NCHUNK];
__device__ int   g_choff[NCHUNK];    // exclusive chunk offsets (published by fill2 blk0)
__device__ float g_norm[MAXN];
__device__ int   g_csr_src[MAXE];
__device__ float g_q[MAXN * 16];     // h2 quarter scratch, 6.4MB

// ---------------------------------------------------------------- histogram (4 edges/thread)
__global__ void k_hist(const int* __restrict__ dst, int E) {
    int base = (blockIdx.x * blockDim.x + threadIdx.x) * 4;
    if (base + 3 < E) {
        int4 d = *(const int4*)(dst + base);
        atomicAdd(&g_deg[d.x], 1);
        atomicAdd(&g_deg[d.y], 1);
        atomicAdd(&g_deg[d.z], 1);
        atomicAdd(&g_deg[d.w], 1);
    } else {
        for (int e = base; e < E; e++) atomicAdd(&g_deg[dst[e]], 1);
    }
}

// ---------------------------------------------------------------- scan1 (shuffle scan + norm + deg re-zero)
__global__ void k_scan1(int N) {
    __shared__ int swarp[32];
    int t = threadIdx.x;                    // 1024 threads
    int i = blockIdx.x * 1024 + t;
    int v = (i < N) ? g_deg[i] : 0;
    if (i < N) {
        g_norm[i] = rsqrtf(fmaxf((float)v, 1.0f));
        g_deg[i] = 0;                       // becomes the fill cursor
    }
    int lane = t & 31, wid = t >> 5;
    int s = v;
    #pragma unroll
    for (int o = 1; o < 32; o <<= 1) {
        int x = __shfl_up_sync(0xffffffffu, s, o);
        if (lane >= o) s += x;
    }
    if (lane == 31) swarp[wid] = s;
    __syncthreads();
    if (wid == 0) {
        int ws = swarp[lane];
        #pragma unroll
        for (int o = 1; o < 32; o <<= 1) {
            int x = __shfl_up_sync(0xffffffffu, ws, o);
            if (lane >= o) ws += x;
        }
        swarp[lane] = ws;                   // inclusive warp totals
    }
    __syncthreads();
    int incl = s + ((wid > 0) ? swarp[wid - 1] : 0);
    if (i < N) g_rowptr[i] = incl - v;      // exclusive, chunk-partial
    if (i == N - 1) g_rowptr[N] = incl;     // partial inclusive at N-1
    if (t == 1023) g_chunksum[blockIdx.x] = incl;   // chunk total
}

// ---------------------------------------------------------------- fill (+chunk-offset finalize)
__global__ void k_fill2(const int* __restrict__ src, const int* __restrict__ dst,
                        int E, int nchunks) {
    __shared__ int soff[NCHUNK];            // inclusive scan of chunk sums
    int t = threadIdx.x;                    // 256 threads
    if (t < NCHUNK) soff[t] = (t < nchunks) ? g_chunksum[t] : 0;
    __syncthreads();
    #pragma unroll
    for (int o = 1; o < NCHUNK; o <<= 1) {
        int x = (t >= o && t < NCHUNK) ? soff[t - o] : 0;
        __syncthreads();
        if (t < NCHUNK) soff[t] += x;
        __syncthreads();
    }
    if (blockIdx.x == 0 && t < NCHUNK)
        g_choff[t] = (t == 0) ? 0 : soff[t - 1];    // exclusive, for consumers
    __syncthreads();

    int base = (blockIdx.x * blockDim.x + t) * 4;
    if (base + 3 < E) {
        int4 d4 = *(const int4*)(dst + base);
        int4 s4 = *(const int4*)(src + base);
        {
            int d = d4.x, c = d >> 10;
            int p = g_rowptr[d] + ((c == 0) ? 0 : soff[c - 1]) + atomicAdd(&g_deg[d], 1);
            g_csr_src[p] = s4.x;
        }
        {
            int d = d4.y, c = d >> 10;
            int p = g_rowptr[d] + ((c == 0) ? 0 : soff[c - 1]) + atomicAdd(&g_deg[d], 1);
            g_csr_src[p] = s4.y;
        }
        {
            int d = d4.z, c = d >> 10;
            int p = g_rowptr[d] + ((c == 0) ? 0 : soff[c - 1]) + atomicAdd(&g_deg[d], 1);
            g_csr_src[p] = s4.z;
        }
        {
            int d = d4.w, c = d >> 10;
            int p = g_rowptr[d] + ((c == 0) ? 0 : soff[c - 1]) + atomicAdd(&g_deg[d], 1);
            g_csr_src[p] = s4.w;
        }
    } else {
        for (int e = base; e < E; e++) {
            int d = dst[e], c = d >> 10;
            int p = g_rowptr[d] + ((c == 0) ? 0 : soff[c - 1]) + atomicAdd(&g_deg[d], 1);
            g_csr_src[p] = src[e];
        }
    }
}

// ---------------------------------------------------------------- hop1 (4th launch -> profiled)
// HALF-WARP per dst row; 16 lanes x float4 = 256B row. 2 rows/warp: one
// issued instruction serves both rows -> ~1.6x fewer warp-iterations.
__global__ void k_hop1s(const float* __restrict__ x, float* __restrict__ y, int N) {
    int idx = blockIdx.x * blockDim.x + threadIdx.x;
    int row = idx >> 4;
    int lh  = idx & 15;
    if (row >= N) return;
    int beg = g_rowptr[row]     + g_choff[row >> 10];
    int end = g_rowptr[row + 1] + g_choff[(row + 1) >> 10];
    float nd = g_norm[row];
    float4 acc = make_float4(0.f, 0.f, 0.f, 0.f);
    const float4* xf = (const float4*)x;
    for (int j = beg; j < end; j++) {
        int   s = __ldg(&g_csr_src[j]);
        float w = __ldg(&g_norm[s]);
        float4 v = xf[s * 16 + lh];
        acc.x += w * v.x; acc.y += w * v.y;
        acc.z += w * v.z; acc.w += w * v.w;
    }
    acc.x *= nd; acc.y *= nd; acc.z *= nd; acc.w *= nd;
    ((float4*)y)[row * 16 + lh] = acc;
}

// ---------------------------------------------------------------- hop2 quarter pass
// 8-LANE group per dst row; lane owns float2 of the 16-col quarter.
// 4 rows/warp -> ~2.75x fewer issued warp-iterations per pass.
// read/write column sets disjoint -> race-free.
__global__ void k_hopq(const float* __restrict__ xsrc, float* ydst,
                       int to_scratch, int N) {
    int idx = blockIdx.x * blockDim.x + threadIdx.x;
    int row = idx >> 3;
    int l8  = idx & 7;
    if (row >= N) return;
    int beg = g_rowptr[row]     + g_choff[row >> 10];
    int end = g_rowptr[row + 1] + g_choff[(row + 1) >> 10];
    float nd = g_norm[row];
    float2 acc = make_float2(0.f, 0.f);
    for (int j = beg; j < end; j++) {
        int   s = __ldg(&g_csr_src[j]);
        float w = __ldg(&g_norm[s]);
        float2 v = *(const float2*)&xsrc[s * F + l8 * 2];
        acc.x += w * v.x;
        acc.y += w * v.y;
    }
    acc.x *= nd;
    acc.y *= nd;
    if (to_scratch) *(float2*)&g_q[row * 16 + l8 * 2] = acc;
    else            *(float2*)&ydst[row * F + l8 * 2] = acc;
}

// ---------------------------------------------------------------- GEMM (in-place, row-local)
// 64-row tile, 256 threads, 4x4 outputs/thread. Ys loads via float4.
// h2 row r = [ g_q[r][0..15] | inout[r][0..47] ]. Tail re-zeros g_deg.
__global__ void k_gemm(float* inout, const float* __restrict__ Wm,
                       const float* __restrict__ bias, int N) {
    __shared__ float Ws[F][F];         // 16KB
    __shared__ float Ys[F][68];        // stride 68: float4-aligned rows
    int t = threadIdx.x;
    int row0 = blockIdx.x * F;
    for (int i = t; i < F * F / 4; i += 256) {
        *(float4*)&((float*)Ws)[i * 4] = *(const float4*)&Wm[i * 4];
    }
    for (int i4 = t; i4 < F * 16; i4 += 256) {      // 16 float4 per row
        int r  = i4 >> 4;
        int c4 = (i4 & 15) * 4;
        int gr = row0 + r;
        float4 v = make_float4(0.f, 0.f, 0.f, 0.f);
        if (gr < N)
            v = (c4 < 16) ? *(const float4*)&g_q[gr * 16 + c4]
                          : *(const float4*)&inout[gr * F + (c4 - 16)];
        *(float4*)&Ys[r][c4] = v;
    }
    __syncthreads();
    int tx = t & 15, ty = t >> 4;
    int c0 = tx * 4, r0 = ty * 4;
    float acc[4][4];
    float4 bv = *(const float4*)&bias[c0];
    #pragma unroll
    for (int i = 0; i < 4; i++) {
        acc[i][0] = bv.x; acc[i][1] = bv.y; acc[i][2] = bv.z; acc[i][3] = bv.w;
    }
    #pragma unroll
    for (int k = 0; k < F; k++) {
        float4 wv = *(const float4*)&Ws[k][c0];
        #pragma unroll
        for (int i = 0; i < 4; i++) {
            float yv = Ys[r0 + i][k];
            acc[i][0] += yv * wv.x;
            acc[i][1] += yv * wv.y;
            acc[i][2] += yv * wv.z;
            acc[i][3] += yv * wv.w;
        }
    }
    #pragma unroll
    for (int i = 0; i < 4; i++) {
        int gr = row0 + r0 + i;
        if (gr < N) {
            float4 v = make_float4(acc[i][0], acc[i][1], acc[i][2], acc[i][3]);
            *(float4*)(inout + gr * F + c0) = v;
        }
    }
    // re-zero the deg/cursor array for the next call (zero-init covers call 1)
    int gi = blockIdx.x * 256 + t;
    if (gi < N) g_deg[gi] = 0;
}

// ---------------------------------------------------------------- launch
// Launches ONLY — no runtime API calls (graph-capture strictness).
extern "C" void kernel_launch(void* const* d_in, const int* in_sizes, int n_in,
                              void* d_out, int out_size) {
    const float* feat = (const float*)d_in[0];
    const int*   src  = (const int*)d_in[1];
    const int*   dst  = (const int*)d_in[2];
    const float* Wm   = (const float*)d_in[3];
    const float* bias = (const float*)d_in[4];
    float* out = (float*)d_out;

    int N = in_sizes[0] / F;   // 100000
    int E = in_sizes[1];       // 1000000

    int nb_e4  = (E / 4 + 255) / 256;
    int nb_sc  = (N + 1023) / 1024;        // 98 chunks
    int nb_h1  = (N * 16 + 255) / 256;     // half-warp per row
    int nb_hq  = (N * 8 + 255) / 256;      // 8-lane group per row
    int nb_gm  = (N + F - 1) / F;

    k_hist  <<<nb_e4, 256>>>(dst, E);
    k_scan1 <<<nb_sc, 1024>>>(N);
    k_fill2 <<<nb_e4, 256>>>(src, dst, E, nb_sc);
    k_hop1s <<<nb_h1, 256>>>(feat, out, N);         // 4th launch: profiled
    // hop2 quarter passes: disjoint column read/write sets, no races
    k_hopq  <<<nb_hq, 256>>>(out + 0,  nullptr,  1, N);  // q0 -> g_q scratch
    k_hopq  <<<nb_hq, 256>>>(out + 16, out + 0,  0, N);  // q1 -> dout.q0
    k_hopq  <<<nb_hq, 256>>>(out + 32, out + 16, 0, N);  // q2 -> dout.q1
    k_hopq  <<<nb_hq, 256>>>(out + 48, out + 32, 0, N);  // q3 -> dout.q2
    k_gemm  <<<nb_gm, 256>>>(out, Wm, bias, N);
}